// round 14
// baseline (speedup 1.0000x reference)
#include <cuda_runtime.h>
#include <cuda_fp16.h>
#include <cuda_bf16.h>

#define N_NODES 100000
#define IN_DIM  256
#define HID     128
#define OUT_DIM 32
#define E_MAX   1600000

// ---------------- device scratch ----------------
__device__ __half g_h0h[(size_t)N_NODES * HID];       // fp16 x@W1+b1
__device__ __half g_h1h[(size_t)N_NODES * HID];       // fp16 relu(A@h0)
__device__ __half g_h2h[(size_t)N_NODES * OUT_DIM];   // fp16 h1@W2+b2
__device__ int   g_cnt[N_NODES];                      // zero at entry (rotated)
__device__ int   g_rowptr[N_NODES + 1];
__device__ int   g_cur[N_NODES];
__device__ int   g_bsum[128];
__device__ int   g_flag[128];                         // zeroed by count each launch
__device__ int2  g_cedge[E_MAX];                      // packed {col, val_bits}

// ---------------------------------------------------------------------------
// mma helpers
// ---------------------------------------------------------------------------
__device__ __forceinline__ void mma_f16(float* d, const unsigned* a, const unsigned* b) {
    asm volatile(
        "mma.sync.aligned.m16n8k16.row.col.f32.f16.f16.f32 "
        "{%0,%1,%2,%3}, {%4,%5,%6,%7}, {%8,%9}, {%0,%1,%2,%3};\n"
        : "+f"(d[0]), "+f"(d[1]), "+f"(d[2]), "+f"(d[3])
        : "r"(a[0]), "r"(a[1]), "r"(a[2]), "r"(a[3]), "r"(b[0]), "r"(b[1]));
}

__device__ __forceinline__ unsigned smem_u32(const void* p) {
    return (unsigned)__cvta_generic_to_shared(p);
}

__device__ __forceinline__ void ldmatrix_x4(unsigned* r, unsigned addr) {
    asm volatile("ldmatrix.sync.aligned.m8n8.x4.shared.b16 {%0,%1,%2,%3}, [%4];"
                 : "=r"(r[0]), "=r"(r[1]), "=r"(r[2]), "=r"(r[3]) : "r"(addr));
}

__device__ __forceinline__ void ldmatrix_x2_trans(unsigned* r, unsigned addr) {
    asm volatile("ldmatrix.sync.aligned.m8n8.x2.trans.shared.b16 {%0,%1}, [%2];"
                 : "=r"(r[0]), "=r"(r[1]) : "r"(addr));
}

// ---------------------------------------------------------------------------
// GEMM1 (fp16 tensor cores, ldmatrix, reg-staged double buffer):
//   g_h0h = half(x @ W1 + b1).  M=100000, K=256, N=128.
// ---------------------------------------------------------------------------
#define BKH 16
#define NITERH (IN_DIM / BKH)   // 16
#define A_LD 24
#define B_LD 136

__global__ __launch_bounds__(256) void gemm1_mma_kernel(const float* __restrict__ X,
                                                        const float* __restrict__ W,
                                                        const float* __restrict__ bias) {
    __shared__ __half Ah[2][128][A_LD];
    __shared__ __half Bh[2][BKH][B_LD];

    const int tid  = threadIdx.x;
    const int wid  = tid >> 5;
    const int lane = tid & 31;
    const int g    = lane >> 2;
    const int t    = lane & 3;
    const int wm   = wid >> 2;
    const int wn   = wid & 3;
    const int block_m = blockIdx.x * 128;

    float acc[4][4][4];
#pragma unroll
    for (int mi = 0; mi < 4; mi++)
#pragma unroll
        for (int ni = 0; ni < 4; ni++)
#pragma unroll
            for (int q = 0; q < 4; q++) acc[mi][ni][q] = 0.0f;

    const int ar = tid >> 1;
    const int ak = (tid & 1) * 8;
    const bool avalid = (block_m + ar) < N_NODES;
    const float* aptr = X + (size_t)(avalid ? block_m + ar : 0) * IN_DIM + ak;
    const int bk = tid >> 4;
    const int bn = (tid & 15) * 8;
    const float* bptr = W + (size_t)bk * HID + bn;

    float4 ra0, ra1, rb0, rb1;

    auto ldg_stage = [&](int k0) {
        if (avalid) {
            ra0 = *(const float4*)(aptr + k0);
            ra1 = *(const float4*)(aptr + k0 + 4);
        } else {
            ra0 = make_float4(0.f, 0.f, 0.f, 0.f);
            ra1 = ra0;
        }
        rb0 = *(const float4*)(bptr + (size_t)k0 * HID);
        rb1 = *(const float4*)(bptr + (size_t)k0 * HID + 4);
    };

    auto sts_stage = [&](int s) {
        __half2 ha[4];
        ha[0] = __floats2half2_rn(ra0.x, ra0.y);
        ha[1] = __floats2half2_rn(ra0.z, ra0.w);
        ha[2] = __floats2half2_rn(ra1.x, ra1.y);
        ha[3] = __floats2half2_rn(ra1.z, ra1.w);
        *(uint4*)&Ah[s][ar][ak] = *(uint4*)ha;
        __half2 hb[4];
        hb[0] = __floats2half2_rn(rb0.x, rb0.y);
        hb[1] = __floats2half2_rn(rb0.z, rb0.w);
        hb[2] = __floats2half2_rn(rb1.x, rb1.y);
        hb[3] = __floats2half2_rn(rb1.z, rb1.w);
        *(uint4*)&Bh[s][bk][bn] = *(uint4*)hb;
    };

    const int a_mloc = (lane & 7) + ((lane >> 3) & 1) * 8;
    const int a_kloc = ((lane >> 4) & 1) * 8;
    const int b_krow = lane & 15;

    ldg_stage(0);
    sts_stage(0);
    __syncthreads();

    for (int it = 0; it < NITERH; it++) {
        const int s = it & 1;
        if (it + 1 < NITERH) ldg_stage((it + 1) * BKH);

        unsigned af[4][4];
        unsigned bf[4][2];
#pragma unroll
        for (int mf = 0; mf < 4; mf++) {
            unsigned addr = smem_u32(&Ah[s][wm * 64 + mf * 16 + a_mloc][a_kloc]);
            ldmatrix_x4(af[mf], addr);
        }
#pragma unroll
        for (int nf = 0; nf < 4; nf++) {
            unsigned addr = smem_u32(&Bh[s][b_krow][wn * 32 + nf * 8]);
            ldmatrix_x2_trans(bf[nf], addr);
        }
#pragma unroll
        for (int mf = 0; mf < 4; mf++)
#pragma unroll
            for (int nf = 0; nf < 4; nf++)
                mma_f16(acc[mf][nf], af[mf], bf[nf]);

        if (it + 1 < NITERH) {
            sts_stage(s ^ 1);
            __syncthreads();
        }
    }

#pragma unroll
    for (int ni = 0; ni < 4; ni++) {
        int n = wn * 32 + ni * 8 + 2 * t;
        float b0 = bias[n], b1 = bias[n + 1];
#pragma unroll
        for (int mi = 0; mi < 4; mi++) {
            int r0 = block_m + wm * 64 + mi * 16 + g;
            int r1 = r0 + 8;
            if (r0 < N_NODES)
                *(__half2*)(g_h0h + (size_t)r0 * HID + n) =
                    __floats2half2_rn(acc[mi][ni][0] + b0, acc[mi][ni][1] + b1);
            if (r1 < N_NODES)
                *(__half2*)(g_h0h + (size_t)r1 * HID + n) =
                    __floats2half2_rn(acc[mi][ni][2] + b0, acc[mi][ni][3] + b1);
        }
    }
}

// ---------------------------------------------------------------------------
// CSR build.  count: 2 coalesced independent atomic chains per thread; also
// zeroes the scan flags (block 0) — ordered before scan by stream order.
// ---------------------------------------------------------------------------
__global__ void csr_count_kernel(const int* __restrict__ erow, int E) {
    if (blockIdx.x == 0 && threadIdx.x < 128) g_flag[threadIdx.x] = 0;
    int h = (E + 1) >> 1;
    int i = blockIdx.x * 256 + threadIdx.x;
    if (i < h) {
        int r0 = erow[i];
        int j = i + h;
        atomicAdd(&g_cnt[r0], 1);
        if (j < E) {
            int r1 = erow[j];
            atomicAdd(&g_cnt[r1], 1);
        }
    }
}

// Single-pass scan with decoupled lookback.  Grid = ceil(N/1024) = 98 blocks,
// all resident (every SM can co-host a scan block even beside gemm1 blocks)
// -> polling is deadlock-free.  Re-zeroes g_cnt, inits g_cur, sets rowptr[N].
__global__ __launch_bounds__(1024) void scan_lb_kernel(int E) {
    __shared__ int s[1024];
    __shared__ int red[128];

    const int t = threadIdx.x;
    const int b = blockIdx.x;
    const int i = b * 1024 + t;

    int v = (i < N_NODES) ? g_cnt[i] : 0;
    s[t] = v;
    for (int off = 1; off < 1024; off <<= 1) {
        __syncthreads();
        int tmp = (t >= off) ? s[t - off] : 0;
        __syncthreads();
        s[t] += tmp;
    }
    __syncthreads();
    const int incl = s[t];

    // publish block total
    if (t == 0) {
        g_bsum[b] = s[1023];
        __threadfence();
        atomicExch(&g_flag[b], 1);
    }

    // lookback: thread t (< b) polls predecessor t
    int contrib = 0;
    if (t < b) {
        while (atomicAdd(&g_flag[t], 0) == 0) { }
        __threadfence();
        contrib = g_bsum[t];
    }
    if (t < 128) red[t] = (t < b) ? contrib : 0;
    __syncthreads();
    // tree reduce 128 -> 1
    for (int off = 64; off > 0; off >>= 1) {
        if (t < off) red[t] += red[t + off];
        __syncthreads();
    }
    const int prefix = red[0];

    if (i < N_NODES) {
        int val = incl - v + prefix;   // exclusive global prefix
        g_rowptr[i] = val;
        g_cur[i] = val;
        g_cnt[i] = 0;                  // re-zero for next launch
    }
    if (b == 0 && t == 0) g_rowptr[N_NODES] = E;
}

// scatter: 2 coalesced independent chains per thread.
__global__ void csr_scatter_kernel(const int* __restrict__ erow,
                                   const int* __restrict__ ecol,
                                   const float* __restrict__ eval, int E) {
    int h = (E + 1) >> 1;
    int i = blockIdx.x * 256 + threadIdx.x;
    if (i < h) {
        int r0 = erow[i];
        int c0 = ecol[i];
        float v0 = eval[i];
        int j = i + h;
        int idx0 = atomicAdd(&g_cur[r0], 1);
        if (j < E) {
            int r1 = erow[j];
            int c1 = ecol[j];
            float v1 = eval[j];
            int idx1 = atomicAdd(&g_cur[r1], 1);
            g_cedge[idx0] = make_int2(c0, __float_as_int(v0));
            g_cedge[idx1] = make_int2(c1, __float_as_int(v1));
        } else {
            g_cedge[idx0] = make_int2(c0, __float_as_int(v0));
        }
    }
}

// ---------------------------------------------------------------------------
// SpMM1 + ReLU: g_h1h[r] = relu(sum_e val * g_h0h[col]).  One warp per row;
// 32 lanes x uint2 (4 halves), 8 edges unrolled -> MLP 8; __ldcg gathers.
// ---------------------------------------------------------------------------
__global__ __launch_bounds__(256) void spmm1_kernel() {
    const int wid  = threadIdx.x >> 5;
    const int lane = threadIdx.x & 31;
    const int r = blockIdx.x * 8 + wid;
    if (r >= N_NODES) return;

    const int s0 = g_rowptr[r];
    const int s1 = g_rowptr[r + 1];

    float acc[4];
#pragma unroll
    for (int i = 0; i < 4; i++) acc[i] = 0.f;

    for (int base = s0; base < s1; base += 32) {
        int cnt = min(32, s1 - base);
        int2 pk = make_int2(0, 0);
        if (lane < cnt) pk = g_cedge[base + lane];

        int j = 0;
        for (; j + 8 <= cnt; j += 8) {
            int   c[8];
            float v[8];
#pragma unroll
            for (int u = 0; u < 8; u++) {
                c[u] = __shfl_sync(0xffffffffu, pk.x, j + u);
                v[u] = __int_as_float(__shfl_sync(0xffffffffu, pk.y, j + u));
            }
            uint2 hw[8];
#pragma unroll
            for (int u = 0; u < 8; u++)
                hw[u] = __ldcg(((const uint2*)(g_h0h + (size_t)c[u] * HID)) + lane);
#pragma unroll
            for (int u = 0; u < 8; u++) {
                float2 f0 = __half22float2(*(__half2*)&hw[u].x);
                float2 f1 = __half22float2(*(__half2*)&hw[u].y);
                acc[0] += v[u] * f0.x; acc[1] += v[u] * f0.y;
                acc[2] += v[u] * f1.x; acc[3] += v[u] * f1.y;
            }
        }
        for (; j + 4 <= cnt; j += 4) {
            int   c[4];
            float v[4];
#pragma unroll
            for (int u = 0; u < 4; u++) {
                c[u] = __shfl_sync(0xffffffffu, pk.x, j + u);
                v[u] = __int_as_float(__shfl_sync(0xffffffffu, pk.y, j + u));
            }
            uint2 hw[4];
#pragma unroll
            for (int u = 0; u < 4; u++)
                hw[u] = __ldcg(((const uint2*)(g_h0h + (size_t)c[u] * HID)) + lane);
#pragma unroll
            for (int u = 0; u < 4; u++) {
                float2 f0 = __half22float2(*(__half2*)&hw[u].x);
                float2 f1 = __half22float2(*(__half2*)&hw[u].y);
                acc[0] += v[u] * f0.x; acc[1] += v[u] * f0.y;
                acc[2] += v[u] * f1.x; acc[3] += v[u] * f1.y;
            }
        }
        for (; j < cnt; j++) {
            int c = __shfl_sync(0xffffffffu, pk.x, j);
            float v = __int_as_float(__shfl_sync(0xffffffffu, pk.y, j));
            uint2 hw = __ldcg(((const uint2*)(g_h0h + (size_t)c * HID)) + lane);
            float2 f0 = __half22float2(*(__half2*)&hw.x);
            float2 f1 = __half22float2(*(__half2*)&hw.y);
            acc[0] += v * f0.x; acc[1] += v * f0.y;
            acc[2] += v * f1.x; acc[3] += v * f1.y;
        }
    }

    __half2 o0 = __floats2half2_rn(fmaxf(acc[0], 0.f), fmaxf(acc[1], 0.f));
    __half2 o1 = __floats2half2_rn(fmaxf(acc[2], 0.f), fmaxf(acc[3], 0.f));
    uint2 pkout = make_uint2(*(unsigned*)&o0, *(unsigned*)&o1);
    ((uint2*)(g_h1h + (size_t)r * HID))[lane] = pkout;
}

// ---------------------------------------------------------------------------
// GEMM2 (fp16 tensor cores): g_h2h = half(g_h1h @ W2 + b2).
// ---------------------------------------------------------------------------
__global__ __launch_bounds__(256) void gemm2_mma_kernel(const float* __restrict__ W2,
                                                        const float* __restrict__ b2) {
    __shared__ uint2 Bfrag[8][4][32];
    __shared__ float b2s[OUT_DIM];

    const int tid  = threadIdx.x;
    const int wid  = tid >> 5;
    const int lane = tid & 31;
    const int g    = lane >> 2;
    const int t    = lane & 3;

    if (tid < 32) {
#pragma unroll
        for (int ks = 0; ks < 8; ks++)
#pragma unroll
            for (int nf = 0; nf < 4; nf++) {
                int k0 = ks * 16 + 2 * t;
                int n  = nf * 8 + g;
                __half2 lo = __floats2half2_rn(W2[(size_t)k0 * OUT_DIM + n],
                                               W2[(size_t)(k0 + 1) * OUT_DIM + n]);
                __half2 hi = __floats2half2_rn(W2[(size_t)(k0 + 8) * OUT_DIM + n],
                                               W2[(size_t)(k0 + 9) * OUT_DIM + n]);
                Bfrag[ks][nf][lane] = make_uint2(*(unsigned*)&lo, *(unsigned*)&hi);
            }
    }
    if (tid < OUT_DIM) b2s[tid] = b2[tid];
    __syncthreads();

    const int r0 = blockIdx.x * 128 + wid * 16 + g;
    const bool v0 = r0 < N_NODES;
    const bool v1 = (r0 + 8) < N_NODES;
    const unsigned* row0 = (const unsigned*)(g_h1h + (size_t)(v0 ? r0 : 0) * HID);
    const unsigned* row1 = (const unsigned*)(g_h1h + (size_t)(v1 ? r0 + 8 : 0) * HID);

    float acc[4][4];
#pragma unroll
    for (int nf = 0; nf < 4; nf++)
#pragma unroll
        for (int q = 0; q < 4; q++) acc[nf][q] = 0.f;

#pragma unroll
    for (int ks = 0; ks < 8; ks++) {
        const int h = ks * 8 + t;
        unsigned a[4];
        a[0] = v0 ? row0[h] : 0u;
        a[1] = v1 ? row1[h] : 0u;
        a[2] = v0 ? row0[h + 4] : 0u;
        a[3] = v1 ? row1[h + 4] : 0u;
#pragma unroll
        for (int nf = 0; nf < 4; nf++) {
            uint2 b = Bfrag[ks][nf][lane];
            unsigned bb[2] = {b.x, b.y};
            mma_f16(acc[nf], a, bb);
        }
    }

#pragma unroll
    for (int nf = 0; nf < 4; nf++) {
        int n = nf * 8 + 2 * t;
        float bb0 = b2s[n], bb1 = b2s[n + 1];
        if (v0)
            *(__half2*)(g_h2h + (size_t)r0 * OUT_DIM + n) =
                __floats2half2_rn(acc[nf][0] + bb0, acc[nf][1] + bb1);
        if (v1)
            *(__half2*)(g_h2h + (size_t)(r0 + 8) * OUT_DIM + n) =
                __floats2half2_rn(acc[nf][2] + bb0, acc[nf][3] + bb1);
    }
}

// ---------------------------------------------------------------------------
// SpMM2: 16 lanes per row (half2 each); halves process alternating edges,
// 8 edges unrolled per half -> MLP 8; __ldcg gathers.
// ---------------------------------------------------------------------------
__global__ __launch_bounds__(256) void spmm2_csr_kernel(float* __restrict__ out) {
    const int wid  = threadIdx.x >> 5;
    const int lane = threadIdx.x & 31;
    const int half = lane >> 4;
    const int l16  = lane & 15;
    const int r = blockIdx.x * 8 + wid;
    if (r >= N_NODES) return;

    const int s0 = g_rowptr[r];
    const int s1 = g_rowptr[r + 1];

    float2 acc = make_float2(0.f, 0.f);
    for (int base = s0; base < s1; base += 32) {
        int cnt = min(32, s1 - base);
        int2 pk = make_int2(0, 0);
        if (lane < cnt) pk = g_cedge[base + lane];

        int j = 0;
        for (; j + 16 <= cnt; j += 16) {
            int   c[8];
            float v[8];
#pragma unroll
            for (int u = 0; u < 8; u++) {
                int e = j + 2 * u + half;
                c[u] = __shfl_sync(0xffffffffu, pk.x, e);
                v[u] = __int_as_float(__shfl_sync(0xffffffffu, pk.y, e));
            }
            unsigned hv[8];
#pragma unroll
            for (int u = 0; u < 8; u++)
                hv[u] = __ldcg(((const unsigned*)(g_h2h + (size_t)c[u] * OUT_DIM)) + l16);
#pragma unroll
            for (int u = 0; u < 8; u++) {
                float2 f = __half22float2(*(__half2*)&hv[u]);
                acc.x += v[u] * f.x;
                acc.y += v[u] * f.y;
            }
        }
        for (; j < cnt; j += 2) {
            int e = j + half;
            int esafe = (e < cnt) ? e : (cnt - 1);
            int c = __shfl_sync(0xffffffffu, pk.x, esafe);
            float v = __int_as_float(__shfl_sync(0xffffffffu, pk.y, esafe));
            if (e >= cnt) v = 0.f;
            unsigned hv = __ldcg(((const unsigned*)(g_h2h + (size_t)c * OUT_DIM)) + l16);
            float2 f = __half22float2(*(__half2*)&hv);
            acc.x += v * f.x;
            acc.y += v * f.y;
        }
    }

    acc.x += __shfl_xor_sync(0xffffffffu, acc.x, 16);
    acc.y += __shfl_xor_sync(0xffffffffu, acc.y, 16);
    if (half == 0)
        *(float2*)(out + (size_t)r * OUT_DIM + 2 * l16) = acc;
}

// ---------------------------------------------------------------------------
// Launch.  CSR chain on side stream (3 kernels); gemm1 on main.
// ---------------------------------------------------------------------------
extern "C" void kernel_launch(void* const* d_in, const int* in_sizes, int n_in,
                              void* d_out, int out_size) {
    const float* x    = (const float*)d_in[0];
    const int*   erow = (const int*)d_in[1];
    const int*   ecol = (const int*)d_in[2];
    const float* eval = (const float*)d_in[3];
    const float* W1   = (const float*)d_in[4];
    const float* b1   = (const float*)d_in[5];
    const float* W2   = (const float*)d_in[6];
    const float* b2   = (const float*)d_in[7];
    float* out = (float*)d_out;
    const int E = in_sizes[1];

    static cudaStream_t s1 = nullptr;
    static cudaEvent_t ev_fork = nullptr, ev_join = nullptr;
    if (s1 == nullptr) {
        cudaStreamCreateWithFlags(&s1, cudaStreamNonBlocking);
        cudaEventCreateWithFlags(&ev_fork, cudaEventDisableTiming);
        cudaEventCreateWithFlags(&ev_join, cudaEventDisableTiming);
    }

    const int halfE     = (E + 1) / 2;
    const int nb_edgeh  = (halfE + 255) / 256;
    const int nb_scan   = (N_NODES + 1023) / 1024;
    const int nb_rows8  = (N_NODES + 7) / 8;

    cudaEventRecord(ev_fork, 0);
    cudaStreamWaitEvent(s1, ev_fork, 0);

    // CSR chain on s1: count -> lookback scan -> scatter
    csr_count_kernel<<<nb_edgeh, 256, 0, s1>>>(erow, E);
    scan_lb_kernel<<<nb_scan, 1024, 0, s1>>>(E);
    csr_scatter_kernel<<<nb_edgeh, 256, 0, s1>>>(erow, ecol, eval, E);
    cudaEventRecord(ev_join, s1);

    // GEMM1 (fp16/ldmatrix) on main stream
    gemm1_mma_kernel<<<(N_NODES + 127) / 128, 256>>>(x, W1, b1);

    // join, then SpMM1 -> GEMM2 -> SpMM2
    cudaStreamWaitEvent(0, ev_join, 0);
    spmm1_kernel<<<nb_rows8, 256>>>();
    gemm2_mma_kernel<<<(N_NODES + 127) / 128, 256>>>(W2, b2);
    spmm2_csr_kernel<<<nb_rows8, 256>>>(out);
}

// round 15
// speedup vs baseline: 1.0458x; 1.0458x over previous
#include <cuda_runtime.h>
#include <cuda_fp16.h>
#include <cuda_bf16.h>

#define N_NODES 100000
#define IN_DIM  256
#define HID     128
#define OUT_DIM 32
#define E_MAX   1600000

// ---------------- device scratch ----------------
__device__ __half g_h0h[(size_t)N_NODES * HID];       // fp16 x@W1+b1
__device__ __half g_h1h[(size_t)N_NODES * HID];       // fp16 relu(A@h0)
__device__ __half g_h2h[(size_t)N_NODES * OUT_DIM];   // fp16 h1@W2+b2
__device__ int   g_cnt[N_NODES];                      // zero at entry (rotated)
__device__ int   g_rowptr[N_NODES + 1];
__device__ int   g_cur[N_NODES];
__device__ int   g_bsum[128];
__device__ int   g_flag[128];                         // zeroed by count each launch
__device__ int   g_done;                              // zeroed by count each launch
__device__ int2  g_cedge[E_MAX];                      // packed {col, val_bits}

// ---------------------------------------------------------------------------
// mma helpers
// ---------------------------------------------------------------------------
__device__ __forceinline__ void mma_f16(float* d, const unsigned* a, const unsigned* b) {
    asm volatile(
        "mma.sync.aligned.m16n8k16.row.col.f32.f16.f16.f32 "
        "{%0,%1,%2,%3}, {%4,%5,%6,%7}, {%8,%9}, {%0,%1,%2,%3};\n"
        : "+f"(d[0]), "+f"(d[1]), "+f"(d[2]), "+f"(d[3])
        : "r"(a[0]), "r"(a[1]), "r"(a[2]), "r"(a[3]), "r"(b[0]), "r"(b[1]));
}

__device__ __forceinline__ unsigned smem_u32(const void* p) {
    return (unsigned)__cvta_generic_to_shared(p);
}

__device__ __forceinline__ void ldmatrix_x4(unsigned* r, unsigned addr) {
    asm volatile("ldmatrix.sync.aligned.m8n8.x4.shared.b16 {%0,%1,%2,%3}, [%4];"
                 : "=r"(r[0]), "=r"(r[1]), "=r"(r[2]), "=r"(r[3]) : "r"(addr));
}

__device__ __forceinline__ void ldmatrix_x2_trans(unsigned* r, unsigned addr) {
    asm volatile("ldmatrix.sync.aligned.m8n8.x2.trans.shared.b16 {%0,%1}, [%2];"
                 : "=r"(r[0]), "=r"(r[1]) : "r"(addr));
}

// ---------------------------------------------------------------------------
// GEMM1 (fp16 tensor cores, ldmatrix, A prefetch-distance-2 reg staging):
//   g_h0h = half(x @ W1 + b1).  M=100000, K=256, N=128.
// ---------------------------------------------------------------------------
#define BKH 16
#define NITERH (IN_DIM / BKH)   // 16
#define A_LD 24
#define B_LD 136

__global__ __launch_bounds__(256, 2) void gemm1_mma_kernel(const float* __restrict__ X,
                                                           const float* __restrict__ W,
                                                           const float* __restrict__ bias) {
    __shared__ __half Ah[2][128][A_LD];
    __shared__ __half Bh[2][BKH][B_LD];

    const int tid  = threadIdx.x;
    const int wid  = tid >> 5;
    const int lane = tid & 31;
    const int g    = lane >> 2;
    const int t    = lane & 3;
    const int wm   = wid >> 2;
    const int wn   = wid & 3;
    const int block_m = blockIdx.x * 128;

    float acc[4][4][4];
#pragma unroll
    for (int mi = 0; mi < 4; mi++)
#pragma unroll
        for (int ni = 0; ni < 4; ni++)
#pragma unroll
            for (int q = 0; q < 4; q++) acc[mi][ni][q] = 0.0f;

    const int ar = tid >> 1;
    const int ak = (tid & 1) * 8;
    const bool avalid = (block_m + ar) < N_NODES;
    const float* aptr = X + (size_t)(avalid ? block_m + ar : 0) * IN_DIM + ak;
    const int bk = tid >> 4;
    const int bn = (tid & 15) * 8;
    const float* bptr = W + (size_t)bk * HID + bn;

    float4 a0, a1;     // A buf0
    float4 pa0, pa1;   // A buf1
    float4 b0, b1;     // B buf

    auto ldgA = [&](int k0, float4& x0, float4& x1) {
        if (avalid) {
            x0 = *(const float4*)(aptr + k0);
            x1 = *(const float4*)(aptr + k0 + 4);
        } else {
            x0 = make_float4(0.f, 0.f, 0.f, 0.f);
            x1 = x0;
        }
    };
    auto ldgB = [&](int k0) {
        b0 = *(const float4*)(bptr + (size_t)k0 * HID);
        b1 = *(const float4*)(bptr + (size_t)k0 * HID + 4);
    };
    auto stsA = [&](int s, const float4& x0, const float4& x1) {
        __half2 ha[4];
        ha[0] = __floats2half2_rn(x0.x, x0.y);
        ha[1] = __floats2half2_rn(x0.z, x0.w);
        ha[2] = __floats2half2_rn(x1.x, x1.y);
        ha[3] = __floats2half2_rn(x1.z, x1.w);
        *(uint4*)&Ah[s][ar][ak] = *(uint4*)ha;
    };
    auto stsB = [&](int s) {
        __half2 hb[4];
        hb[0] = __floats2half2_rn(b0.x, b0.y);
        hb[1] = __floats2half2_rn(b0.z, b0.w);
        hb[2] = __floats2half2_rn(b1.x, b1.y);
        hb[3] = __floats2half2_rn(b1.z, b1.w);
        *(uint4*)&Bh[s][bk][bn] = *(uint4*)hb;
    };

    const int a_mloc = (lane & 7) + ((lane >> 3) & 1) * 8;
    const int a_kloc = ((lane >> 4) & 1) * 8;
    const int b_krow = lane & 15;

    auto compute = [&](int s) {
        unsigned af[4][4];
        unsigned bf[4][2];
#pragma unroll
        for (int mf = 0; mf < 4; mf++) {
            unsigned addr = smem_u32(&Ah[s][wm * 64 + mf * 16 + a_mloc][a_kloc]);
            ldmatrix_x4(af[mf], addr);
        }
#pragma unroll
        for (int nf = 0; nf < 4; nf++) {
            unsigned addr = smem_u32(&Bh[s][b_krow][wn * 32 + nf * 8]);
            ldmatrix_x2_trans(bf[nf], addr);
        }
#pragma unroll
        for (int mf = 0; mf < 4; mf++)
#pragma unroll
            for (int nf = 0; nf < 4; nf++)
                mma_f16(acc[mf][nf], af[mf], bf[nf]);
    };

    // prologue: smem stage0, A-prefetch stage1
    ldgA(0, a0, a1);
    ldgB(0);
    stsA(0, a0, a1);
    stsB(0);
    ldgA(BKH, pa0, pa1);     // buf1 := stage 1
    __syncthreads();

#pragma unroll
    for (int it = 0; it < NITERH; it += 2) {
        // even stage (smem 0)
        if (it + 2 < NITERH) ldgA((it + 2) * BKH, a0, a1);   // buf0 := it+2
        ldgB((it + 1) * BKH);
        compute(0);
        stsA(1, pa0, pa1);   // stage it+1 (loaded at it-1)
        stsB(1);
        __syncthreads();
        // odd stage (smem 1)
        if (it + 3 < NITERH) ldgA((it + 3) * BKH, pa0, pa1); // buf1 := it+3
        if (it + 2 < NITERH) ldgB((it + 2) * BKH);
        compute(1);
        if (it + 2 < NITERH) {
            stsA(0, a0, a1);
            stsB(0);
            __syncthreads();
        }
    }

#pragma unroll
    for (int ni = 0; ni < 4; ni++) {
        int n = wn * 32 + ni * 8 + 2 * t;
        float bb0 = bias[n], bb1 = bias[n + 1];
#pragma unroll
        for (int mi = 0; mi < 4; mi++) {
            int r0 = block_m + wm * 64 + mi * 16 + g;
            int r1 = r0 + 8;
            if (r0 < N_NODES)
                *(__half2*)(g_h0h + (size_t)r0 * HID + n) =
                    __floats2half2_rn(acc[mi][ni][0] + bb0, acc[mi][ni][1] + bb1);
            if (r1 < N_NODES)
                *(__half2*)(g_h0h + (size_t)r1 * HID + n) =
                    __floats2half2_rn(acc[mi][ni][2] + bb0, acc[mi][ni][3] + bb1);
        }
    }
}

// ---------------------------------------------------------------------------
// CSR build.  count: 2 coalesced chains/thread; zeroes scan flags + done ctr.
// ---------------------------------------------------------------------------
__global__ void csr_count_kernel(const int* __restrict__ erow, int E) {
    if (blockIdx.x == 0) {
        if (threadIdx.x < 128) g_flag[threadIdx.x] = 0;
        if (threadIdx.x == 128) g_done = 0;
    }
    int h = (E + 1) >> 1;
    int i = blockIdx.x * 256 + threadIdx.x;
    if (i < h) {
        int r0 = erow[i];
        int j = i + h;
        atomicAdd(&g_cnt[r0], 1);
        if (j < E) {
            int r1 = erow[j];
            atomicAdd(&g_cnt[r1], 1);
        }
    }
}

// Fused lookback-scan + scatter.  98 blocks x 1024 thr, all resident ->
// flag polling + done-counter grid sync are deadlock-free.
__global__ __launch_bounds__(1024) void scan_scatter_kernel(const int* __restrict__ erow,
                                                            const int* __restrict__ ecol,
                                                            const float* __restrict__ eval,
                                                            int E) {
    __shared__ int s[1024];
    __shared__ int red[128];

    const int t = threadIdx.x;
    const int b = blockIdx.x;
    const int i = b * 1024 + t;

    // ---- phase 1: scan ----
    int v = (i < N_NODES) ? g_cnt[i] : 0;
    s[t] = v;
    for (int off = 1; off < 1024; off <<= 1) {
        __syncthreads();
        int tmp = (t >= off) ? s[t - off] : 0;
        __syncthreads();
        s[t] += tmp;
    }
    __syncthreads();
    const int incl = s[t];

    if (t == 0) {
        g_bsum[b] = s[1023];
        __threadfence();
        atomicExch(&g_flag[b], 1);
    }

    int contrib = 0;
    if (t < b) {
        while (atomicAdd(&g_flag[t], 0) == 0) { }
        __threadfence();
        contrib = g_bsum[t];
    }
    if (t < 128) red[t] = (t < b) ? contrib : 0;
    __syncthreads();
    for (int off = 64; off > 0; off >>= 1) {
        if (t < off) red[t] += red[t + off];
        __syncthreads();
    }
    const int prefix = red[0];

    if (i < N_NODES) {
        int val = incl - v + prefix;
        g_rowptr[i] = val;
        g_cur[i] = val;
        g_cnt[i] = 0;
    }
    if (b == 0 && t == 0) g_rowptr[N_NODES] = E;

    // ---- grid sync via done counter ----
    __syncthreads();
    if (t == 0) {
        __threadfence();
        atomicAdd(&g_done, 1);
        while (atomicAdd(&g_done, 0) < (int)gridDim.x) { }
    }
    __syncthreads();
    __threadfence();

    // ---- phase 2: scatter (grid-stride, coalesced) ----
    const int stride = (int)gridDim.x * 1024;
    for (int e = b * 1024 + t; e < E; e += stride) {
        int r = erow[e];
        int c = ecol[e];
        float vv = eval[e];
        int idx = atomicAdd(&g_cur[r], 1);
        g_cedge[idx] = make_int2(c, __float_as_int(vv));
    }
}

// ---------------------------------------------------------------------------
// SpMM1 + ReLU: g_h1h[r] = relu(sum_e val * g_h0h[col]).  One warp per row;
// 32 lanes x uint2 (4 halves), 8 edges unrolled -> MLP 8; plain (L1) loads.
// ---------------------------------------------------------------------------
__global__ __launch_bounds__(256) void spmm1_kernel() {
    const int wid  = threadIdx.x >> 5;
    const int lane = threadIdx.x & 31;
    const int r = blockIdx.x * 8 + wid;
    if (r >= N_NODES) return;

    const int s0 = g_rowptr[r];
    const int s1 = g_rowptr[r + 1];

    float acc[4];
#pragma unroll
    for (int i = 0; i < 4; i++) acc[i] = 0.f;

    for (int base = s0; base < s1; base += 32) {
        int cnt = min(32, s1 - base);
        int2 pk = make_int2(0, 0);
        if (lane < cnt) pk = g_cedge[base + lane];

        int j = 0;
        for (; j + 8 <= cnt; j += 8) {
            int   c[8];
            float v[8];
#pragma unroll
            for (int u = 0; u < 8; u++) {
                c[u] = __shfl_sync(0xffffffffu, pk.x, j + u);
                v[u] = __int_as_float(__shfl_sync(0xffffffffu, pk.y, j + u));
            }
            uint2 hw[8];
#pragma unroll
            for (int u = 0; u < 8; u++)
                hw[u] = ((const uint2*)(g_h0h + (size_t)c[u] * HID))[lane];
#pragma unroll
            for (int u = 0; u < 8; u++) {
                float2 f0 = __half22float2(*(__half2*)&hw[u].x);
                float2 f1 = __half22float2(*(__half2*)&hw[u].y);
                acc[0] += v[u] * f0.x; acc[1] += v[u] * f0.y;
                acc[2] += v[u] * f1.x; acc[3] += v[u] * f1.y;
            }
        }
        for (; j + 4 <= cnt; j += 4) {
            int   c[4];
            float v[4];
#pragma unroll
            for (int u = 0; u < 4; u++) {
                c[u] = __shfl_sync(0xffffffffu, pk.x, j + u);
                v[u] = __int_as_float(__shfl_sync(0xffffffffu, pk.y, j + u));
            }
            uint2 hw[4];
#pragma unroll
            for (int u = 0; u < 4; u++)
                hw[u] = ((const uint2*)(g_h0h + (size_t)c[u] * HID))[lane];
#pragma unroll
            for (int u = 0; u < 4; u++) {
                float2 f0 = __half22float2(*(__half2*)&hw[u].x);
                float2 f1 = __half22float2(*(__half2*)&hw[u].y);
                acc[0] += v[u] * f0.x; acc[1] += v[u] * f0.y;
                acc[2] += v[u] * f1.x; acc[3] += v[u] * f1.y;
            }
        }
        for (; j < cnt; j++) {
            int c = __shfl_sync(0xffffffffu, pk.x, j);
            float v = __int_as_float(__shfl_sync(0xffffffffu, pk.y, j));
            uint2 hw = ((const uint2*)(g_h0h + (size_t)c * HID))[lane];
            float2 f0 = __half22float2(*(__half2*)&hw.x);
            float2 f1 = __half22float2(*(__half2*)&hw.y);
            acc[0] += v * f0.x; acc[1] += v * f0.y;
            acc[2] += v * f1.x; acc[3] += v * f1.y;
        }
    }

    __half2 o0 = __floats2half2_rn(fmaxf(acc[0], 0.f), fmaxf(acc[1], 0.f));
    __half2 o1 = __floats2half2_rn(fmaxf(acc[2], 0.f), fmaxf(acc[3], 0.f));
    uint2 pkout = make_uint2(*(unsigned*)&o0, *(unsigned*)&o1);
    ((uint2*)(g_h1h + (size_t)r * HID))[lane] = pkout;
}

// ---------------------------------------------------------------------------
// GEMM2 (fp16 tensor cores): g_h2h = half(g_h1h @ W2 + b2).
// ---------------------------------------------------------------------------
__global__ __launch_bounds__(256) void gemm2_mma_kernel(const float* __restrict__ W2,
                                                        const float* __restrict__ b2) {
    __shared__ uint2 Bfrag[8][4][32];
    __shared__ float b2s[OUT_DIM];

    const int tid  = threadIdx.x;
    const int wid  = tid >> 5;
    const int lane = tid & 31;
    const int g    = lane >> 2;
    const int t    = lane & 3;

    if (tid < 32) {
#pragma unroll
        for (int ks = 0; ks < 8; ks++)
#pragma unroll
            for (int nf = 0; nf < 4; nf++) {
                int k0 = ks * 16 + 2 * t;
                int n  = nf * 8 + g;
                __half2 lo = __floats2half2_rn(W2[(size_t)k0 * OUT_DIM + n],
                                               W2[(size_t)(k0 + 1) * OUT_DIM + n]);
                __half2 hi = __floats2half2_rn(W2[(size_t)(k0 + 8) * OUT_DIM + n],
                                               W2[(size_t)(k0 + 9) * OUT_DIM + n]);
                Bfrag[ks][nf][lane] = make_uint2(*(unsigned*)&lo, *(unsigned*)&hi);
            }
    }
    if (tid < OUT_DIM) b2s[tid] = b2[tid];
    __syncthreads();

    const int r0 = blockIdx.x * 128 + wid * 16 + g;
    const bool v0 = r0 < N_NODES;
    const bool v1 = (r0 + 8) < N_NODES;
    const unsigned* row0 = (const unsigned*)(g_h1h + (size_t)(v0 ? r0 : 0) * HID);
    const unsigned* row1 = (const unsigned*)(g_h1h + (size_t)(v1 ? r0 + 8 : 0) * HID);

    float acc[4][4];
#pragma unroll
    for (int nf = 0; nf < 4; nf++)
#pragma unroll
        for (int q = 0; q < 4; q++) acc[nf][q] = 0.f;

#pragma unroll
    for (int ks = 0; ks < 8; ks++) {
        const int h = ks * 8 + t;
        unsigned a[4];
        a[0] = v0 ? row0[h] : 0u;
        a[1] = v1 ? row1[h] : 0u;
        a[2] = v0 ? row0[h + 4] : 0u;
        a[3] = v1 ? row1[h + 4] : 0u;
#pragma unroll
        for (int nf = 0; nf < 4; nf++) {
            uint2 b = Bfrag[ks][nf][lane];
            unsigned bb[2] = {b.x, b.y};
            mma_f16(acc[nf], a, bb);
        }
    }

#pragma unroll
    for (int nf = 0; nf < 4; nf++) {
        int n = nf * 8 + 2 * t;
        float bb0 = b2s[n], bb1 = b2s[n + 1];
        if (v0)
            *(__half2*)(g_h2h + (size_t)r0 * OUT_DIM + n) =
                __floats2half2_rn(acc[nf][0] + bb0, acc[nf][1] + bb1);
        if (v1)
            *(__half2*)(g_h2h + (size_t)(r0 + 8) * OUT_DIM + n) =
                __floats2half2_rn(acc[nf][2] + bb0, acc[nf][3] + bb1);
    }
}

// ---------------------------------------------------------------------------
// SpMM2: 16 lanes per row (half2 each); halves process alternating edges,
// 8 edges unrolled per half -> MLP 8; plain (L1) loads.
// ---------------------------------------------------------------------------
__global__ __launch_bounds__(256) void spmm2_csr_kernel(float* __restrict__ out) {
    const int wid  = threadIdx.x >> 5;
    const int lane = threadIdx.x & 31;
    const int half = lane >> 4;
    const int l16  = lane & 15;
    const int r = blockIdx.x * 8 + wid;
    if (r >= N_NODES) return;

    const int s0 = g_rowptr[r];
    const int s1 = g_rowptr[r + 1];

    float2 acc = make_float2(0.f, 0.f);
    for (int base = s0; base < s1; base += 32) {
        int cnt = min(32, s1 - base);
        int2 pk = make_int2(0, 0);
        if (lane < cnt) pk = g_cedge[base + lane];

        int j = 0;
        for (; j + 16 <= cnt; j += 16) {
            int   c[8];
            float v[8];
#pragma unroll
            for (int u = 0; u < 8; u++) {
                int e = j + 2 * u + half;
                c[u] = __shfl_sync(0xffffffffu, pk.x, e);
                v[u] = __int_as_float(__shfl_sync(0xffffffffu, pk.y, e));
            }
            __half2 hv[8];
#pragma unroll
            for (int u = 0; u < 8; u++)
                hv[u] = ((const __half2*)(g_h2h + (size_t)c[u] * OUT_DIM))[l16];
#pragma unroll
            for (int u = 0; u < 8; u++) {
                float2 f = __half22float2(hv[u]);
                acc.x += v[u] * f.x;
                acc.y += v[u] * f.y;
            }
        }
        for (; j < cnt; j += 2) {
            int e = j + half;
            int esafe = (e < cnt) ? e : (cnt - 1);
            int c = __shfl_sync(0xffffffffu, pk.x, esafe);
            float v = __int_as_float(__shfl_sync(0xffffffffu, pk.y, esafe));
            if (e >= cnt) v = 0.f;
            __half2 hv = ((const __half2*)(g_h2h + (size_t)c * OUT_DIM))[l16];
            float2 f = __half22float2(hv);
            acc.x += v * f.x;
            acc.y += v * f.y;
        }
    }

    acc.x += __shfl_xor_sync(0xffffffffu, acc.x, 16);
    acc.y += __shfl_xor_sync(0xffffffffu, acc.y, 16);
    if (half == 0)
        *(float2*)(out + (size_t)r * OUT_DIM + 2 * l16) = acc;
}

// ---------------------------------------------------------------------------
// Launch.  CSR chain (2 kernels) on side stream; gemm1 on main.
// Submission order: count(1), scan_scatter(2), gemm1(3), spmm1(4 <- ncu slot).
// ---------------------------------------------------------------------------
extern "C" void kernel_launch(void* const* d_in, const int* in_sizes, int n_in,
                              void* d_out, int out_size) {
    const float* x    = (const float*)d_in[0];
    const int*   erow = (const int*)d_in[1];
    const int*   ecol = (const int*)d_in[2];
    const float* eval = (const float*)d_in[3];
    const float* W1   = (const float*)d_in[4];
    const float* b1   = (const float*)d_in[5];
    const float* W2   = (const float*)d_in[6];
    const float* b2   = (const float*)d_in[7];
    float* out = (float*)d_out;
    const int E = in_sizes[1];

    static cudaStream_t s1 = nullptr;
    static cudaEvent_t ev_fork = nullptr, ev_join = nullptr;
    if (s1 == nullptr) {
        cudaStreamCreateWithFlags(&s1, cudaStreamNonBlocking);
        cudaEventCreateWithFlags(&ev_fork, cudaEventDisableTiming);
        cudaEventCreateWithFlags(&ev_join, cudaEventDisableTiming);
    }

    const int halfE    = (E + 1) / 2;
    const int nb_edgeh = (halfE + 255) / 256;
    const int nb_scan  = (N_NODES + 1023) / 1024;   // 98
    const int nb_rows8 = (N_NODES + 7) / 8;

    cudaEventRecord(ev_fork, 0);
    cudaStreamWaitEvent(s1, ev_fork, 0);

    // CSR chain on s1: count -> fused scan+scatter
    csr_count_kernel<<<nb_edgeh, 256, 0, s1>>>(erow, E);
    scan_scatter_kernel<<<nb_scan, 1024, 0, s1>>>(erow, ecol, eval, E);
    cudaEventRecord(ev_join, s1);

    // GEMM1 (fp16/ldmatrix, prefetch-2) on main stream
    gemm1_mma_kernel<<<(N_NODES + 127) / 128, 256>>>(x, W1, b1);

    // join, then SpMM1 -> GEMM2 -> SpMM2
    cudaStreamWaitEvent(0, ev_join, 0);
    spmm1_kernel<<<nb_rows8, 256>>>();
    gemm2_mma_kernel<<<(N_NODES + 127) / 128, 256>>>(W2, b2);
    spmm2_csr_kernel<<<nb_rows8, 256>>>(out);
}

// round 16
// speedup vs baseline: 1.1828x; 1.1309x over previous
#include <cuda_runtime.h>
#include <cuda_fp16.h>
#include <cuda_bf16.h>

#define N_NODES 100000
#define IN_DIM  256
#define HID     128
#define OUT_DIM 32
#define E_MAX   1600000

// ---------------- device scratch ----------------
__device__ __half g_h0h[(size_t)N_NODES * HID];       // fp16 x@W1+b1
__device__ __half g_h1h[(size_t)N_NODES * HID];       // fp16 relu(A@h0)
__device__ __half g_h2h[(size_t)N_NODES * OUT_DIM];   // fp16 h1@W2+b2
__device__ int   g_cnt[N_NODES];                      // zero at entry (rotated)
__device__ int   g_rowptr[N_NODES + 1];
__device__ int   g_cur[N_NODES];
__device__ int   g_bsum[128];
__device__ int   g_flag[128];                         // zeroed by count each launch
__device__ int   g_done;                              // zeroed by count each launch
__device__ int2  g_cedge[E_MAX];                      // packed {col, half2(v,v) bits}

// ---------------------------------------------------------------------------
// mma helpers
// ---------------------------------------------------------------------------
__device__ __forceinline__ void mma_f16(float* d, const unsigned* a, const unsigned* b) {
    asm volatile(
        "mma.sync.aligned.m16n8k16.row.col.f32.f16.f16.f32 "
        "{%0,%1,%2,%3}, {%4,%5,%6,%7}, {%8,%9}, {%0,%1,%2,%3};\n"
        : "+f"(d[0]), "+f"(d[1]), "+f"(d[2]), "+f"(d[3])
        : "r"(a[0]), "r"(a[1]), "r"(a[2]), "r"(a[3]), "r"(b[0]), "r"(b[1]));
}

__device__ __forceinline__ unsigned smem_u32(const void* p) {
    return (unsigned)__cvta_generic_to_shared(p);
}

__device__ __forceinline__ void ldmatrix_x4(unsigned* r, unsigned addr) {
    asm volatile("ldmatrix.sync.aligned.m8n8.x4.shared.b16 {%0,%1,%2,%3}, [%4];"
                 : "=r"(r[0]), "=r"(r[1]), "=r"(r[2]), "=r"(r[3]) : "r"(addr));
}

__device__ __forceinline__ void ldmatrix_x2_trans(unsigned* r, unsigned addr) {
    asm volatile("ldmatrix.sync.aligned.m8n8.x2.trans.shared.b16 {%0,%1}, [%2];"
                 : "=r"(r[0]), "=r"(r[1]) : "r"(addr));
}

// ---------------------------------------------------------------------------
// GEMM1 (fp16 tensor cores, ldmatrix, A prefetch-distance-2 reg staging):
//   g_h0h = half(x @ W1 + b1).  M=100000, K=256, N=128.
// ---------------------------------------------------------------------------
#define BKH 16
#define NITERH (IN_DIM / BKH)   // 16
#define A_LD 24
#define B_LD 136

__global__ __launch_bounds__(256, 2) void gemm1_mma_kernel(const float* __restrict__ X,
                                                           const float* __restrict__ W,
                                                           const float* __restrict__ bias) {
    __shared__ __half Ah[2][128][A_LD];
    __shared__ __half Bh[2][BKH][B_LD];

    const int tid  = threadIdx.x;
    const int wid  = tid >> 5;
    const int lane = tid & 31;
    const int g    = lane >> 2;
    const int t    = lane & 3;
    const int wm   = wid >> 2;
    const int wn   = wid & 3;
    const int block_m = blockIdx.x * 128;

    float acc[4][4][4];
#pragma unroll
    for (int mi = 0; mi < 4; mi++)
#pragma unroll
        for (int ni = 0; ni < 4; ni++)
#pragma unroll
            for (int q = 0; q < 4; q++) acc[mi][ni][q] = 0.0f;

    const int ar = tid >> 1;
    const int ak = (tid & 1) * 8;
    const bool avalid = (block_m + ar) < N_NODES;
    const float* aptr = X + (size_t)(avalid ? block_m + ar : 0) * IN_DIM + ak;
    const int bk = tid >> 4;
    const int bn = (tid & 15) * 8;
    const float* bptr = W + (size_t)bk * HID + bn;

    float4 a0, a1;     // A buf0
    float4 pa0, pa1;   // A buf1
    float4 b0, b1;     // B buf

    auto ldgA = [&](int k0, float4& x0, float4& x1) {
        if (avalid) {
            x0 = *(const float4*)(aptr + k0);
            x1 = *(const float4*)(aptr + k0 + 4);
        } else {
            x0 = make_float4(0.f, 0.f, 0.f, 0.f);
            x1 = x0;
        }
    };
    auto ldgB = [&](int k0) {
        b0 = *(const float4*)(bptr + (size_t)k0 * HID);
        b1 = *(const float4*)(bptr + (size_t)k0 * HID + 4);
    };
    auto stsA = [&](int s, const float4& x0, const float4& x1) {
        __half2 ha[4];
        ha[0] = __floats2half2_rn(x0.x, x0.y);
        ha[1] = __floats2half2_rn(x0.z, x0.w);
        ha[2] = __floats2half2_rn(x1.x, x1.y);
        ha[3] = __floats2half2_rn(x1.z, x1.w);
        *(uint4*)&Ah[s][ar][ak] = *(uint4*)ha;
    };
    auto stsB = [&](int s) {
        __half2 hb[4];
        hb[0] = __floats2half2_rn(b0.x, b0.y);
        hb[1] = __floats2half2_rn(b0.z, b0.w);
        hb[2] = __floats2half2_rn(b1.x, b1.y);
        hb[3] = __floats2half2_rn(b1.z, b1.w);
        *(uint4*)&Bh[s][bk][bn] = *(uint4*)hb;
    };

    const int a_mloc = (lane & 7) + ((lane >> 3) & 1) * 8;
    const int a_kloc = ((lane >> 4) & 1) * 8;
    const int b_krow = lane & 15;

    auto compute = [&](int s) {
        unsigned af[4][4];
        unsigned bf[4][2];
#pragma unroll
        for (int mf = 0; mf < 4; mf++) {
            unsigned addr = smem_u32(&Ah[s][wm * 64 + mf * 16 + a_mloc][a_kloc]);
            ldmatrix_x4(af[mf], addr);
        }
#pragma unroll
        for (int nf = 0; nf < 4; nf++) {
            unsigned addr = smem_u32(&Bh[s][b_krow][wn * 32 + nf * 8]);
            ldmatrix_x2_trans(bf[nf], addr);
        }
#pragma unroll
        for (int mf = 0; mf < 4; mf++)
#pragma unroll
            for (int nf = 0; nf < 4; nf++)
                mma_f16(acc[mf][nf], af[mf], bf[nf]);
    };

    ldgA(0, a0, a1);
    ldgB(0);
    stsA(0, a0, a1);
    stsB(0);
    ldgA(BKH, pa0, pa1);
    __syncthreads();

#pragma unroll
    for (int it = 0; it < NITERH; it += 2) {
        if (it + 2 < NITERH) ldgA((it + 2) * BKH, a0, a1);
        ldgB((it + 1) * BKH);
        compute(0);
        stsA(1, pa0, pa1);
        stsB(1);
        __syncthreads();
        if (it + 3 < NITERH) ldgA((it + 3) * BKH, pa0, pa1);
        if (it + 2 < NITERH) ldgB((it + 2) * BKH);
        compute(1);
        if (it + 2 < NITERH) {
            stsA(0, a0, a1);
            stsB(0);
            __syncthreads();
        }
    }

#pragma unroll
    for (int ni = 0; ni < 4; ni++) {
        int n = wn * 32 + ni * 8 + 2 * t;
        float bb0 = bias[n], bb1 = bias[n + 1];
#pragma unroll
        for (int mi = 0; mi < 4; mi++) {
            int r0 = block_m + wm * 64 + mi * 16 + g;
            int r1 = r0 + 8;
            if (r0 < N_NODES)
                *(__half2*)(g_h0h + (size_t)r0 * HID + n) =
                    __floats2half2_rn(acc[mi][ni][0] + bb0, acc[mi][ni][1] + bb1);
            if (r1 < N_NODES)
                *(__half2*)(g_h0h + (size_t)r1 * HID + n) =
                    __floats2half2_rn(acc[mi][ni][2] + bb0, acc[mi][ni][3] + bb1);
        }
    }
}

// ---------------------------------------------------------------------------
// CSR build.  count: 2 coalesced chains/thread; zeroes scan flags + done ctr.
// ---------------------------------------------------------------------------
__global__ void csr_count_kernel(const int* __restrict__ erow, int E) {
    if (blockIdx.x == 0) {
        if (threadIdx.x < 128) g_flag[threadIdx.x] = 0;
        if (threadIdx.x == 128) g_done = 0;
    }
    int h = (E + 1) >> 1;
    int i = blockIdx.x * 256 + threadIdx.x;
    if (i < h) {
        int r0 = erow[i];
        int j = i + h;
        atomicAdd(&g_cnt[r0], 1);
        if (j < E) {
            int r1 = erow[j];
            atomicAdd(&g_cnt[r1], 1);
        }
    }
}

// Fused lookback-scan + scatter.  98 blocks x 1024 thr, all resident ->
// flag polling + done-counter grid sync are deadlock-free.
// Scatter packs edge value as half2(v,v) for HFMA2 consumers.
__global__ __launch_bounds__(1024) void scan_scatter_kernel(const int* __restrict__ erow,
                                                            const int* __restrict__ ecol,
                                                            const float* __restrict__ eval,
                                                            int E) {
    __shared__ int s[1024];
    __shared__ int red[128];

    const int t = threadIdx.x;
    const int b = blockIdx.x;
    const int i = b * 1024 + t;

    // ---- phase 1: scan ----
    int v = (i < N_NODES) ? g_cnt[i] : 0;
    s[t] = v;
    for (int off = 1; off < 1024; off <<= 1) {
        __syncthreads();
        int tmp = (t >= off) ? s[t - off] : 0;
        __syncthreads();
        s[t] += tmp;
    }
    __syncthreads();
    const int incl = s[t];

    if (t == 0) {
        g_bsum[b] = s[1023];
        __threadfence();
        atomicExch(&g_flag[b], 1);
    }

    int contrib = 0;
    if (t < b) {
        while (atomicAdd(&g_flag[t], 0) == 0) { }
        __threadfence();
        contrib = g_bsum[t];
    }
    if (t < 128) red[t] = (t < b) ? contrib : 0;
    __syncthreads();
    for (int off = 64; off > 0; off >>= 1) {
        if (t < off) red[t] += red[t + off];
        __syncthreads();
    }
    const int prefix = red[0];

    if (i < N_NODES) {
        int val = incl - v + prefix;
        g_rowptr[i] = val;
        g_cur[i] = val;
        g_cnt[i] = 0;
    }
    if (b == 0 && t == 0) g_rowptr[N_NODES] = E;

    // ---- grid sync via done counter ----
    __syncthreads();
    if (t == 0) {
        __threadfence();
        atomicAdd(&g_done, 1);
        while (atomicAdd(&g_done, 0) < (int)gridDim.x) { }
    }
    __syncthreads();
    __threadfence();

    // ---- phase 2: scatter (grid-stride, coalesced) ----
    const int stride = (int)gridDim.x * 1024;
    for (int e = b * 1024 + t; e < E; e += stride) {
        int r = erow[e];
        int c = ecol[e];
        float vv = eval[e];
        __half2 vh = __floats2half2_rn(vv, vv);
        int idx = atomicAdd(&g_cur[r], 1);
        g_cedge[idx] = make_int2(c, (int)*(unsigned*)&vh);
    }
}

// ---------------------------------------------------------------------------
// SpMM1 + ReLU: g_h1h[r] = relu(sum_e val * g_h0h[col]).  One warp per row;
// edges staged in smem (LDS broadcast, no shfl); HFMA2 fp16 partials folded
// into fp32 every 4 edges.  32 lanes x uint2 (4 halves), 8 loads in flight.
// ---------------------------------------------------------------------------
__global__ __launch_bounds__(256) void spmm1_kernel() {
    __shared__ int2 es[8][32];

    const int wid  = threadIdx.x >> 5;
    const int lane = threadIdx.x & 31;
    const int r = blockIdx.x * 8 + wid;
    if (r >= N_NODES) return;

    const int s0 = g_rowptr[r];
    const int s1 = g_rowptr[r + 1];

    float facc[4];
#pragma unroll
    for (int i = 0; i < 4; i++) facc[i] = 0.f;

    const __half2 hzero = __float2half2_rn(0.f);

    for (int base = s0; base < s1; base += 32) {
        int cnt = min(32, s1 - base);
        __syncwarp();
        if (lane < cnt) es[wid][lane] = g_cedge[base + lane];
        __syncwarp();

        int j = 0;
        for (; j + 8 <= cnt; j += 8) {
            int2 e[8];
#pragma unroll
            for (int u = 0; u < 8; u++) e[u] = es[wid][j + u];
            uint2 hw[8];
#pragma unroll
            for (int u = 0; u < 8; u++)
                hw[u] = ((const uint2*)(g_h0h + (size_t)e[u].x * HID))[lane];
            // two fp16 fold-groups of 4 edges
#pragma unroll
            for (int grp = 0; grp < 2; grp++) {
                __half2 h0 = hzero, h1 = hzero;
#pragma unroll
                for (int u = grp * 4; u < grp * 4 + 4; u++) {
                    __half2 v2 = *(__half2*)&e[u].y;
                    h0 = __hfma2(*(__half2*)&hw[u].x, v2, h0);
                    h1 = __hfma2(*(__half2*)&hw[u].y, v2, h1);
                }
                float2 f0 = __half22float2(h0);
                float2 f1 = __half22float2(h1);
                facc[0] += f0.x; facc[1] += f0.y;
                facc[2] += f1.x; facc[3] += f1.y;
            }
        }
        for (; j + 4 <= cnt; j += 4) {
            int2 e[4];
#pragma unroll
            for (int u = 0; u < 4; u++) e[u] = es[wid][j + u];
            uint2 hw[4];
#pragma unroll
            for (int u = 0; u < 4; u++)
                hw[u] = ((const uint2*)(g_h0h + (size_t)e[u].x * HID))[lane];
            __half2 h0 = hzero, h1 = hzero;
#pragma unroll
            for (int u = 0; u < 4; u++) {
                __half2 v2 = *(__half2*)&e[u].y;
                h0 = __hfma2(*(__half2*)&hw[u].x, v2, h0);
                h1 = __hfma2(*(__half2*)&hw[u].y, v2, h1);
            }
            float2 f0 = __half22float2(h0);
            float2 f1 = __half22float2(h1);
            facc[0] += f0.x; facc[1] += f0.y;
            facc[2] += f1.x; facc[3] += f1.y;
        }
        for (; j < cnt; j++) {
            int2 e = es[wid][j];
            float v = __low2float(*(__half2*)&e.y);
            uint2 hw = ((const uint2*)(g_h0h + (size_t)e.x * HID))[lane];
            float2 f0 = __half22float2(*(__half2*)&hw.x);
            float2 f1 = __half22float2(*(__half2*)&hw.y);
            facc[0] += v * f0.x; facc[1] += v * f0.y;
            facc[2] += v * f1.x; facc[3] += v * f1.y;
        }
    }

    __half2 o0 = __floats2half2_rn(fmaxf(facc[0], 0.f), fmaxf(facc[1], 0.f));
    __half2 o1 = __floats2half2_rn(fmaxf(facc[2], 0.f), fmaxf(facc[3], 0.f));
    uint2 pkout = make_uint2(*(unsigned*)&o0, *(unsigned*)&o1);
    ((uint2*)(g_h1h + (size_t)r * HID))[lane] = pkout;
}

// ---------------------------------------------------------------------------
// GEMM2 (fp16 tensor cores): g_h2h = half(g_h1h @ W2 + b2).
// ---------------------------------------------------------------------------
__global__ __launch_bounds__(256) void gemm2_mma_kernel(const float* __restrict__ W2,
                                                        const float* __restrict__ b2) {
    __shared__ uint2 Bfrag[8][4][32];
    __shared__ float b2s[OUT_DIM];

    const int tid  = threadIdx.x;
    const int wid  = tid >> 5;
    const int lane = tid & 31;
    const int g    = lane >> 2;
    const int t    = lane & 3;

    if (tid < 32) {
#pragma unroll
        for (int ks = 0; ks < 8; ks++)
#pragma unroll
            for (int nf = 0; nf < 4; nf++) {
                int k0 = ks * 16 + 2 * t;
                int n  = nf * 8 + g;
                __half2 lo = __floats2half2_rn(W2[(size_t)k0 * OUT_DIM + n],
                                               W2[(size_t)(k0 + 1) * OUT_DIM + n]);
                __half2 hi = __floats2half2_rn(W2[(size_t)(k0 + 8) * OUT_DIM + n],
                                               W2[(size_t)(k0 + 9) * OUT_DIM + n]);
                Bfrag[ks][nf][lane] = make_uint2(*(unsigned*)&lo, *(unsigned*)&hi);
            }
    }
    if (tid < OUT_DIM) b2s[tid] = b2[tid];
    __syncthreads();

    const int r0 = blockIdx.x * 128 + wid * 16 + g;
    const bool v0 = r0 < N_NODES;
    const bool v1 = (r0 + 8) < N_NODES;
    const unsigned* row0 = (const unsigned*)(g_h1h + (size_t)(v0 ? r0 : 0) * HID);
    const unsigned* row1 = (const unsigned*)(g_h1h + (size_t)(v1 ? r0 + 8 : 0) * HID);

    float acc[4][4];
#pragma unroll
    for (int nf = 0; nf < 4; nf++)
#pragma unroll
        for (int q = 0; q < 4; q++) acc[nf][q] = 0.f;

#pragma unroll
    for (int ks = 0; ks < 8; ks++) {
        const int h = ks * 8 + t;
        unsigned a[4];
        a[0] = v0 ? row0[h] : 0u;
        a[1] = v1 ? row1[h] : 0u;
        a[2] = v0 ? row0[h + 4] : 0u;
        a[3] = v1 ? row1[h + 4] : 0u;
#pragma unroll
        for (int nf = 0; nf < 4; nf++) {
            uint2 b = Bfrag[ks][nf][lane];
            unsigned bb[2] = {b.x, b.y};
            mma_f16(acc[nf], a, bb);
        }
    }

#pragma unroll
    for (int nf = 0; nf < 4; nf++) {
        int n = nf * 8 + 2 * t;
        float bb0 = b2s[n], bb1 = b2s[n + 1];
        if (v0)
            *(__half2*)(g_h2h + (size_t)r0 * OUT_DIM + n) =
                __floats2half2_rn(acc[nf][0] + bb0, acc[nf][1] + bb1);
        if (v1)
            *(__half2*)(g_h2h + (size_t)(r0 + 8) * OUT_DIM + n) =
                __floats2half2_rn(acc[nf][2] + bb0, acc[nf][3] + bb1);
    }
}

// ---------------------------------------------------------------------------
// SpMM2: 16 lanes per row (one half2 = 2 cols each); halves process
// alternating edges; smem edge staging; HFMA2 partials folded every 4 edges.
// ---------------------------------------------------------------------------
__global__ __launch_bounds__(256) void spmm2_csr_kernel(float* __restrict__ out) {
    __shared__ int2 es[8][32];

    const int wid  = threadIdx.x >> 5;
    const int lane = threadIdx.x & 31;
    const int half = lane >> 4;
    const int l16  = lane & 15;
    const int r = blockIdx.x * 8 + wid;
    if (r >= N_NODES) return;

    const int s0 = g_rowptr[r];
    const int s1 = g_rowptr[r + 1];

    float2 facc = make_float2(0.f, 0.f);
    const __half2 hzero = __float2half2_rn(0.f);

    for (int base = s0; base < s1; base += 32) {
        int cnt = min(32, s1 - base);
        __syncwarp();
        if (lane < cnt) es[wid][lane] = g_cedge[base + lane];
        __syncwarp();

        int j = 0;
        for (; j + 16 <= cnt; j += 16) {
            int2 e[8];
#pragma unroll
            for (int u = 0; u < 8; u++) e[u] = es[wid][j + 2 * u + half];
            unsigned hv[8];
#pragma unroll
            for (int u = 0; u < 8; u++)
                hv[u] = ((const unsigned*)(g_h2h + (size_t)e[u].x * OUT_DIM))[l16];
#pragma unroll
            for (int grp = 0; grp < 2; grp++) {
                __half2 h = hzero;
#pragma unroll
                for (int u = grp * 4; u < grp * 4 + 4; u++)
                    h = __hfma2(*(__half2*)&hv[u], *(__half2*)&e[u].y, h);
                float2 f = __half22float2(h);
                facc.x += f.x;
                facc.y += f.y;
            }
        }
        // tail: plain per-edge fp32 (no warp-collective ops -> divergence OK)
        for (; j < cnt; j += 2) {
            int e = j + half;
            if (e < cnt) {
                int2 ed = es[wid][e];
                float v = __low2float(*(__half2*)&ed.y);
                unsigned hv = ((const unsigned*)(g_h2h + (size_t)ed.x * OUT_DIM))[l16];
                float2 f = __half22float2(*(__half2*)&hv);
                facc.x += v * f.x;
                facc.y += v * f.y;
            }
        }
    }

    facc.x += __shfl_xor_sync(0xffffffffu, facc.x, 16);
    facc.y += __shfl_xor_sync(0xffffffffu, facc.y, 16);
    if (half == 0)
        *(float2*)(out + (size_t)r * OUT_DIM + 2 * l16) = facc;
}

// ---------------------------------------------------------------------------
// Launch.  CSR chain (2 kernels) on side stream; gemm1 on main.
// Submission order: count(1), scan_scatter(2), gemm1(3), spmm1(4 <- ncu slot).
// ---------------------------------------------------------------------------
extern "C" void kernel_launch(void* const* d_in, const int* in_sizes, int n_in,
                              void* d_out, int out_size) {
    const float* x    = (const float*)d_in[0];
    const int*   erow = (const int*)d_in[1];
    const int*   ecol = (const int*)d_in[2];
    const float* eval = (const float*)d_in[3];
    const float* W1   = (const float*)d_in[4];
    const float* b1   = (const float*)d_in[5];
    const float* W2   = (const float*)d_in[6];
    const float* b2   = (const float*)d_in[7];
    float* out = (float*)d_out;
    const int E = in_sizes[1];

    static cudaStream_t s1 = nullptr;
    static cudaEvent_t ev_fork = nullptr, ev_join = nullptr;
    if (s1 == nullptr) {
        cudaStreamCreateWithFlags(&s1, cudaStreamNonBlocking);
        cudaEventCreateWithFlags(&ev_fork, cudaEventDisableTiming);
        cudaEventCreateWithFlags(&ev_join, cudaEventDisableTiming);
    }

    const int halfE    = (E + 1) / 2;
    const int nb_edgeh = (halfE + 255) / 256;
    const int nb_scan  = (N_NODES + 1023) / 1024;   // 98
    const int nb_rows8 = (N_NODES + 7) / 8;

    cudaEventRecord(ev_fork, 0);
    cudaStreamWaitEvent(s1, ev_fork, 0);

    // CSR chain on s1: count -> fused scan+scatter
    csr_count_kernel<<<nb_edgeh, 256, 0, s1>>>(erow, E);
    scan_scatter_kernel<<<nb_scan, 1024, 0, s1>>>(erow, ecol, eval, E);
    cudaEventRecord(ev_join, s1);

    // GEMM1 (fp16/ldmatrix, prefetch-2) on main stream
    gemm1_mma_kernel<<<(N_NODES + 127) / 128, 256>>>(x, W1, b1);

    // join, then SpMM1 -> GEMM2 -> SpMM2
    cudaStreamWaitEvent(0, ev_join, 0);
    spmm1_kernel<<<nb_rows8, 256>>>();
    gemm2_mma_kernel<<<(N_NODES + 127) / 128, 256>>>(W2, b2);
    spmm2_csr_kernel<<<nb_rows8, 256>>>(out);
}